// round 7
// baseline (speedup 1.0000x reference)
#include <cuda_runtime.h>
#include <cstdint>

#define FULL 0xffffffffu

constexpr int WPB = 4;   // warps per block

#define FMA_F32X2(out, a, b, c) \
    asm("fma.rn.f32x2 %0, %1, %2, %3;" : "=l"(out) : "l"(a), "l"(b), "l"(c))

__device__ __forceinline__ float warpSum(float v) {
    v += __shfl_xor_sync(FULL, v, 16);
    v += __shfl_xor_sync(FULL, v, 8);
    v += __shfl_xor_sync(FULL, v, 4);
    v += __shfl_xor_sync(FULL, v, 2);
    v += __shfl_xor_sync(FULL, v, 1);
    return v;
}
__device__ __forceinline__ float warpMin(float v) {
    #pragma unroll
    for (int o = 16; o > 0; o >>= 1) v = fminf(v, __shfl_xor_sync(FULL, v, o));
    return v;
}

// One warp per molecule.
// Phase 1: Gram via wrap-diagonals: lane i computes dot(row_i, row_{(i+d)&31})
//          for d=0..16 (only unique entries + 16 dups; ~half the work of full
//          rows). Peer rows via XOR-swizzled conflict-free LDS.128; packed
//          f32x2 FMA. Full row reassembled via conflict-free shared transpose.
// Phase 2: Householder tridiag, A register-resident, fully unrolled.
// Phase 3: Sturm bisection on [0, min diag(T)].
__global__ __launch_bounds__(128, 8) void corr_eig_kernel(
    const float* __restrict__ sr, float* __restrict__ out, int M)
{
    // shBuf serves two phases (disjoint lifetimes):
    //   phase-1 staging: float4[32][8], slot r*8 + (g ^ (r&7))   (first 4KB)
    //   transpose:       float A[32][36]                          (full 4.5KB)
    __shared__ float  shBuf[WPB][32 * 36];
    __shared__ float  shV[WPB][2][32];
    __shared__ float  shW[WPB][2][32];
    __shared__ float2 shDE[WPB][32];

    const int w    = threadIdx.x >> 5;
    const int lane = threadIdx.x & 31;
    const int mol  = blockIdx.x * WPB + w;
    if (mol >= M) return;

    float*      Af  = shBuf[w];
    ulonglong2* G2s = reinterpret_cast<ulonglong2*>(Af);

    // ---------------- Phase 1: Gram wrap-diagonals ----------------
    float sd[17];
    #pragma unroll
    for (int d = 0; d < 17; d++) sd[d] = 0.f;

    // Own row: 128 floats = 32 x ulonglong2; chunk c covers feats [32c, 32c+32)
    const ulonglong2* g2 =
        reinterpret_cast<const ulonglong2*>(sr) + ((size_t)mol * 32 + lane) * 32;
    const int m7 = lane & 7;

    #pragma unroll 1
    for (int c = 0; c < 4; c++) {
        ulonglong2 xv[8];                      // own 32-feat chunk
        #pragma unroll
        for (int i = 0; i < 8; i++) xv[i] = g2[c * 8 + i];

        __syncwarp();                          // prior chunk reads done
        #pragma unroll
        for (int g = 0; g < 8; g++) G2s[lane * 8 + (g ^ m7)] = xv[g];
        __syncwarp();

        // d = 0: self dot, straight from registers
        {
            unsigned long long acc = 0ull;
            #pragma unroll
            for (int g = 0; g < 8; g++) {
                FMA_F32X2(acc, xv[g].x, xv[g].x, acc);
                FMA_F32X2(acc, xv[g].y, xv[g].y, acc);
            }
            float s0, s1;
            asm("mov.b64 {%0,%1}, %2;" : "=f"(s0), "=f"(s1) : "l"(acc));
            sd[0] += s0 + s1;
        }
        // d = 1..16: rotated peer row, conflict-free swizzled LDS.128
        #pragma unroll
        for (int d = 1; d < 17; d++) {
            const int r  = (lane + d) & 31;
            const int mr = r & 7;
            const ulonglong2* row = &G2s[r * 8];
            unsigned long long acc = 0ull;
            #pragma unroll
            for (int g = 0; g < 8; g++) {
                ulonglong2 y = row[g ^ mr];
                FMA_F32X2(acc, xv[g].x, y.x, acc);
                FMA_F32X2(acc, xv[g].y, y.y, acc);
            }
            float s0, s1;
            asm("mov.b64 {%0,%1}, %2;" : "=f"(s0), "=f"(s1) : "l"(acc));
            sd[d] += s0 + s1;
        }
    }

    // Transpose wrap-diagonals into full rows A[i][j] (stride 36, aliases G2s).
    // Banks: (5*lane + d) & 31 resp. (5*lane + 36d) & 31 -> permutations, CF.
    __syncwarp();
    #pragma unroll
    for (int d = 0; d < 17; d++) Af[lane * 36 + ((lane + d) & 31)] = sd[d];
    #pragma unroll
    for (int d = 1; d < 16; d++) Af[((lane + d) & 31) * 36 + lane] = sd[d];
    __syncwarp();

    float a[32];
    #pragma unroll
    for (int q = 0; q < 8; q++) {
        float4 t = *reinterpret_cast<const float4*>(&Af[lane * 36 + 4 * q]);
        a[4 * q + 0] = t.x; a[4 * q + 1] = t.y;
        a[4 * q + 2] = t.z; a[4 * q + 3] = t.w;
    }

    // ---------------- Phase 2: Householder tridiagonalization ----------------
    float d_reg = 0.f, e_reg = 0.f;

    #pragma unroll
    for (int k = 0; k < 30; k++) {
        const bool act = (lane > k);

        // Trailing norm of own row (only lane k's value used), 2 chains
        float sc0 = 0.f, sc1 = 0.f;
        #pragma unroll
        for (int j = k + 1; j < 32; j++) {
            if (j & 1) sc1 = fmaf(a[j], a[j], sc1);
            else       sc0 = fmaf(a[j], a[j], sc0);
        }
        float sigma = __shfl_sync(FULL, sc0 + sc1, k);
        float x1    = __shfl_sync(FULL, a[k + 1], k);   // A[k][k+1]

        float alpha = -copysignf(sqrtf(sigma), x1);
        bool  ok    = (sigma > 1e-20f);
        float beta  = ok ? 1.0f / (sigma - alpha * x1) : 0.f;   // 2 / v^T v
        if (lane == k) { d_reg = a[k]; e_reg = ok ? alpha : x1; }

        float v = act ? a[k] : 0.f;
        if (lane == k + 1) v = ok ? (x1 - alpha) : 0.f;

        float* sV = shV[w][k & 1];
        float* sW = shW[w][k & 1];
        sV[lane] = v;
        __syncwarp();

        // p = beta * (A v): V via broadcast LDS.128
        float pc0 = 0.f, pc1 = 0.f, pc2 = 0.f, pc3 = 0.f;
        #pragma unroll
        for (int jq = (k + 1) >> 2; jq < 8; jq++) {
            float4 v4 = *reinterpret_cast<const float4*>(&sV[4 * jq]);
            pc0 = fmaf(a[4 * jq + 0], v4.x, pc0);
            pc1 = fmaf(a[4 * jq + 1], v4.y, pc1);
            pc2 = fmaf(a[4 * jq + 2], v4.z, pc2);
            pc3 = fmaf(a[4 * jq + 3], v4.w, pc3);
        }
        float p = ((pc0 + pc1) + (pc2 + pc3));
        p = act ? p * beta : 0.f;

        float s  = warpSum(p * v);                     // p^T v
        float wv = p - (0.5f * beta * s) * v;          // 0 on inactive lanes

        sW[lane] = wv;
        __syncwarp();

        // A <- A - v w^T - w v^T
        #pragma unroll
        for (int jq = (k + 1) >> 2; jq < 8; jq++) {
            float4 v4 = *reinterpret_cast<const float4*>(&sV[4 * jq]);
            float4 w4 = *reinterpret_cast<const float4*>(&sW[4 * jq]);
            a[4 * jq + 0] -= v * w4.x + wv * v4.x;
            a[4 * jq + 1] -= v * w4.y + wv * v4.y;
            a[4 * jq + 2] -= v * w4.z + wv * v4.z;
            a[4 * jq + 3] -= v * w4.w + wv * v4.w;
        }
    }
    if (lane == 30) { d_reg = a[30]; e_reg = a[31]; }
    if (lane == 31) { d_reg = a[31]; e_reg = 0.f; }

    // ---------------- Phase 3: Sturm bisection ----------------
    // C is PSD => lambda_min in [0, min_i T_ii].
    __syncwarp();
    shDE[w][lane] = make_float2(d_reg, e_reg * e_reg);
    __syncwarp();
    const float4* DE4 = reinterpret_cast<const float4*>(shDE[w]);  // (d,e2)

    float lo = 0.f;
    float hi = warpMin(d_reg) * 1.0001f;

    #pragma unroll 1
    for (int r = 0; r < 4; r++) {
        float h = (hi - lo) * (1.0f / 33.0f);
        float x = fmaf(h, (float)(lane + 1), lo);

        float4 t = DE4[0];                       // d0, e2_0, d1, e2_1
        float q   = t.x - x;
        int   cnt = (q < 0.f);
        float eprev = t.y;
        {
            float qn = (t.z - x) - __fdividef(eprev, q);
            if (qn == 0.f) qn = -1e-30f;
            cnt += (qn < 0.f);
            q = qn; eprev = t.w;
        }
        #pragma unroll
        for (int m = 1; m < 16; m++) {
            t = DE4[m];
            float qn = (t.x - x) - __fdividef(eprev, q);
            if (qn == 0.f) qn = -1e-30f;
            cnt += (qn < 0.f);
            q = qn; eprev = t.y;

            qn = (t.z - x) - __fdividef(eprev, q);
            if (qn == 0.f) qn = -1e-30f;
            cnt += (qn < 0.f);
            q = qn; eprev = t.w;
        }

        unsigned mask = __ballot_sync(FULL, cnt >= 1);
        int j0 = mask ? (__ffs(mask) - 1) : 32;
        lo += h * (float)j0;
        hi  = lo + h;
    }

    if (lane == 0) out[mol] = 0.5f * (lo + hi);
}

extern "C" void kernel_launch(void* const* d_in, const int* in_sizes, int n_in,
                              void* d_out, int out_size) {
    const float* sr = (const float*)d_in[0];
    // d_in[1] (idx_m) unused: uniform groups -> [M, 32, 128]
    float* out = (float*)d_out;
    int M = in_sizes[0] >> 12;   // / (32*128)

    int blocks = (M + WPB - 1) / WPB;
    corr_eig_kernel<<<blocks, 128>>>(sr, out, M);
}

// round 8
// speedup vs baseline: 1.2901x; 1.2901x over previous
#include <cuda_runtime.h>
#include <cstdint>

#define FULL 0xffffffffu

constexpr int WPB = 4;   // warps per block

typedef unsigned long long u64t;

#define FMA2(d, a, b, c) \
    asm("fma.rn.f32x2 %0, %1, %2, %3;" : "=l"(d) : "l"(a), "l"(b), "l"(c))
#define ADD2(d, a, b) \
    asm("add.rn.f32x2 %0, %1, %2;" : "=l"(d) : "l"(a), "l"(b))

__device__ __forceinline__ u64t pack2(float lo, float hi) {
    u64t r; asm("mov.b64 %0, {%1, %2};" : "=l"(r) : "f"(lo), "f"(hi)); return r;
}
__device__ __forceinline__ void unpack2(u64t p, float& lo, float& hi) {
    asm("mov.b64 {%0, %1}, %2;" : "=f"(lo), "=f"(hi) : "l"(p));
}

__device__ __forceinline__ float warpSum(float v) {
    v += __shfl_xor_sync(FULL, v, 16);
    v += __shfl_xor_sync(FULL, v, 8);
    v += __shfl_xor_sync(FULL, v, 4);
    v += __shfl_xor_sync(FULL, v, 2);
    v += __shfl_xor_sync(FULL, v, 1);
    return v;
}
__device__ __forceinline__ float warpMin(float v) {
    #pragma unroll
    for (int o = 16; o > 0; o >>= 1) v = fminf(v, __shfl_xor_sync(FULL, v, o));
    return v;
}

// One warp per molecule. R3 skeleton + f32x2-packed Householder row.
// Phase 1: Gram C = G G^T, 4 x 32-feat chunks, broadcast LDS.128 row reads,
//          packed f32x2 FMA. Row of C accumulated as 16 packed pairs A2[16].
// Phase 2: Householder tridiag, fully unrolled, all row math in f32x2.
// Phase 3: Sturm bisection on [0, min diag(T)], 3 rounds of 32 probes.
__global__ __launch_bounds__(128, 5) void corr_eig_kernel(
    const float* __restrict__ sr, float* __restrict__ out, int M)
{
    __shared__ __align__(16) float  shG[WPB][32 * 36];  // stride 36: CF stores
    __shared__ __align__(16) float  shV[WPB][2][32];    // double-buffered
    __shared__ __align__(16) float  shW[WPB][2][32];
    __shared__ __align__(16) float2 shDE[WPB][32];

    const int w    = threadIdx.x >> 5;
    const int lane = threadIdx.x & 31;
    const int mol  = blockIdx.x * WPB + w;
    if (mol >= M) return;

    float* G = shG[w];

    // ---------------- Phase 1: Gram ----------------
    u64t A2[16];                               // packed row of C: (a2m, a2m+1)
    #pragma unroll
    for (int m = 0; m < 16; m++) A2[m] = 0ull;

    const ulonglong2* g2 =
        reinterpret_cast<const ulonglong2*>(sr) + ((size_t)mol * 32 + lane) * 32;

    #pragma unroll 1
    for (int c = 0; c < 4; c++) {
        ulonglong2 xv[8];                      // own 32-feat chunk
        #pragma unroll
        for (int i = 0; i < 8; i++) xv[i] = g2[c * 8 + i];

        __syncwarp();                          // prior chunk reads done
        #pragma unroll
        for (int i = 0; i < 8; i++)
            *reinterpret_cast<ulonglong2*>(&G[lane * 36 + 4 * i]) = xv[i];
        __syncwarp();

        #pragma unroll 2
        for (int jp = 0; jp < 16; jp++) {      // pair of rows (2jp, 2jp+1)
            const float* r0 = &G[(2 * jp)     * 36];
            const float* r1 = &G[(2 * jp + 1) * 36];
            u64t acc0 = 0ull, acc1 = 0ull;
            #pragma unroll
            for (int i = 0; i < 8; i++) {
                ulonglong2 y0 = *reinterpret_cast<const ulonglong2*>(r0 + 4 * i);
                ulonglong2 y1 = *reinterpret_cast<const ulonglong2*>(r1 + 4 * i);
                FMA2(acc0, xv[i].x, y0.x, acc0);
                FMA2(acc0, xv[i].y, y0.y, acc0);
                FMA2(acc1, xv[i].x, y1.x, acc1);
                FMA2(acc1, xv[i].y, y1.y, acc1);
            }
            float u0, u1, v0, v1;
            unpack2(acc0, u0, u1);
            unpack2(acc1, v0, v1);
            u64t p = pack2(u0, v0), q = pack2(u1, v1), t;
            ADD2(t, p, q);
            ADD2(A2[jp], A2[jp], t);
        }
    }

    // ---------------- Phase 2: Householder tridiagonalization ----------------
    // Lane i owns row i (packed). Inactive lanes have v = w = 0: rows freeze.
    // sV/sW entries for j <= k are 0 -> packed over-reads contribute nothing.
    float d_reg = 0.f, e_reg = 0.f;

    #pragma unroll
    for (int k = 0; k < 30; k++) {
        const bool act = (lane > k);

        // sigma = sum_{j>k} a_j^2 (only lane k's value consumed)
        u64t S0 = 0ull, S1 = 0ull;
        if ((k & 1) == 0) {                      // pair k/2 holds (a_k, a_{k+1})
            u64t b = A2[k >> 1] & 0xFFFFFFFF00000000ull;   // keep a_{k+1}
            FMA2(S0, b, b, S0);
        }
        #pragma unroll
        for (int m = (k >> 1) + 1; m < 16; m++) {
            if (m & 1) { FMA2(S1, A2[m], A2[m], S1); }
            else       { FMA2(S0, A2[m], A2[m], S0); }
        }
        float s0l, s0h, s1l, s1h;
        unpack2(S0, s0l, s0h); unpack2(S1, s1l, s1h);
        float sig_loc = (s0l + s0h) + (s1l + s1h);

        // own a_k, a_{k+1} (static extraction)
        float ak, ak1;
        if ((k & 1) == 0) {
            unpack2(A2[k >> 1], ak, ak1);
        } else {
            float t0, t1;
            unpack2(A2[k >> 1], t0, ak);
            unpack2(A2[(k >> 1) + 1], ak1, t1);
        }

        float sigma = __shfl_sync(FULL, sig_loc, k);
        float x1    = __shfl_sync(FULL, ak1, k);       // A[k][k+1]

        float alpha = -copysignf(sqrtf(sigma), x1);
        bool  ok    = (sigma > 1e-20f);
        float beta  = ok ? 1.0f / (sigma - alpha * x1) : 0.f;   // 2 / v^T v
        if (lane == k) { d_reg = ak; e_reg = ok ? alpha : x1; }

        float v = act ? ak : 0.f;
        if (lane == k + 1) v = ok ? (x1 - alpha) : 0.f;

        float* sV = shV[w][k & 1];
        float* sW = shW[w][k & 1];
        sV[lane] = v;
        __syncwarp();

        // p = beta * (A v): packed dot, V read as 2 packed pairs per LDS.128
        u64t P0 = 0ull, P1 = 0ull;
        #pragma unroll
        for (int jq = (k + 1) >> 2; jq < 8; jq++) {
            ulonglong2 V2 = *reinterpret_cast<const ulonglong2*>(&sV[4 * jq]);
            FMA2(P0, A2[2 * jq],     V2.x, P0);
            FMA2(P1, A2[2 * jq + 1], V2.y, P1);
        }
        float p0l, p0h, p1l, p1h;
        unpack2(P0, p0l, p0h); unpack2(P1, p1l, p1h);
        float p = (p0l + p0h) + (p1l + p1h);
        p = act ? p * beta : 0.f;

        float s  = warpSum(p * v);                     // p^T v
        float wv = p - (0.5f * beta * s) * v;          // 0 on inactive lanes

        sW[lane] = wv;
        __syncwarp();

        // A <- A - v w^T - w v^T   (packed: 2 FFMA2 per pair)
        u64t nv2 = pack2(-v, -v), nw2 = pack2(-wv, -wv);
        #pragma unroll
        for (int jq = (k + 1) >> 2; jq < 8; jq++) {
            ulonglong2 V2 = *reinterpret_cast<const ulonglong2*>(&sV[4 * jq]);
            ulonglong2 W2 = *reinterpret_cast<const ulonglong2*>(&sW[4 * jq]);
            u64t t;
            FMA2(t, nw2, V2.x, A2[2 * jq]);
            FMA2(A2[2 * jq], nv2, W2.x, t);
            FMA2(t, nw2, V2.y, A2[2 * jq + 1]);
            FMA2(A2[2 * jq + 1], nv2, W2.y, t);
        }
    }
    if (lane == 30) unpack2(A2[15], d_reg, e_reg);     // a30, a31
    if (lane == 31) { float t; unpack2(A2[15], t, d_reg); e_reg = 0.f; }

    // ---------------- Phase 3: Sturm bisection ----------------
    // C is PSD => lambda_min in [0, min_i T_ii].
    __syncwarp();
    shDE[w][lane] = make_float2(d_reg, e_reg * e_reg);
    __syncwarp();
    const float4* DE4 = reinterpret_cast<const float4*>(shDE[w]);  // (d,e2)

    float lo = 0.f;
    float hi = warpMin(d_reg) * 1.0001f;

    #pragma unroll 1
    for (int r = 0; r < 3; r++) {
        float h = (hi - lo) * (1.0f / 33.0f);
        float x = fmaf(h, (float)(lane + 1), lo);

        float4 t = DE4[0];                       // d0, e2_0, d1, e2_1
        float q   = t.x - x;
        int   cnt = (q < 0.f);
        float eprev = t.y;
        {
            float qn = (t.z - x) - __fdividef(eprev, q);
            if (qn == 0.f) qn = -1e-30f;
            cnt += (qn < 0.f);
            q = qn; eprev = t.w;
        }
        #pragma unroll
        for (int m = 1; m < 16; m++) {
            t = DE4[m];
            float qn = (t.x - x) - __fdividef(eprev, q);
            if (qn == 0.f) qn = -1e-30f;
            cnt += (qn < 0.f);
            q = qn; eprev = t.y;

            qn = (t.z - x) - __fdividef(eprev, q);
            if (qn == 0.f) qn = -1e-30f;
            cnt += (qn < 0.f);
            q = qn; eprev = t.w;
        }

        unsigned mask = __ballot_sync(FULL, cnt >= 1);
        int j0 = mask ? (__ffs(mask) - 1) : 32;
        lo += h * (float)j0;
        hi  = lo + h;
    }

    if (lane == 0) out[mol] = 0.5f * (lo + hi);
}

extern "C" void kernel_launch(void* const* d_in, const int* in_sizes, int n_in,
                              void* d_out, int out_size) {
    const float* sr = (const float*)d_in[0];
    // d_in[1] (idx_m) unused: uniform groups -> [M, 32, 128]
    float* out = (float*)d_out;
    int M = in_sizes[0] >> 12;   // / (32*128)

    int blocks = (M + WPB - 1) / WPB;
    corr_eig_kernel<<<blocks, 128>>>(sr, out, M);
}